// round 12
// baseline (speedup 1.0000x reference)
#include <cuda_runtime.h>
#include <cuda_fp16.h>
#include <cstdint>

// Shapes
#define N_Q    65536
#define DIM    64
#define K_EMB  1024
#define QB     128         // queries per sub-block (8 warps x 16 rows)
#define THREADS 256
#define GRID   256         // CTAs; each handles SUBS sub-blocks
#define SUBS   2
#define NGROUP 128
#define PAD    68

#define ESCALE      1024.0f
#define INV_2SCALE  (1.0f / 512.0f)

#define OUT_QV_ELEMS  (64ULL * 64ULL * 32ULL * 32ULL)   // 4194304
#define OUT_IDX_OFF   4194304ULL
#define OUT_LOSS_OFF  4259840ULL

// ---- dynamic smem layout (byte offsets) ----
#define SRED_OFF    0        // double[8]
#define SCNT_OFF    64
#define SLAST_OFF   68
#define SMAXE_OFF   72
#define SIDX_OFF    80       // int[128]
#define SFQ_OFF     592      // int[128]
#define SFBI_OFF    1104     // int[128]
#define SFBEST_OFF  1616     // float[128]
#define SSZ_OFF     2176     // float[128]
#define SSE_OFF     2688     // float[1024]
#define SBUF_OFF    6784     // float[128*68] z tile
#define SE_OFF      41600    // float[128*68] codebook chunk / gathered rows
#define SMEM_MAIN   76416

// device scratch (no cudaMalloc; zero-initialized at load)
__device__ float    g_se2[K_EMB];
__device__ float    g_maxNorm[4];
__device__ uint4    g_b4[NGROUP * 2 * 32];
__device__ double   g_partial[GRID];
__device__ unsigned g_done;                  // monotonic; 2^32 % 256 == 0

__device__ __forceinline__ uint32_t pack_h2(__half lo, __half hi) {
    __half2 h = __halves2half2(lo, hi);
    return *reinterpret_cast<uint32_t*>(&h);
}

__device__ __forceinline__ void mma_f16(float& d0, float& d1, float& d2, float& d3,
                                        uint32_t a0, uint32_t a1, uint32_t a2, uint32_t a3,
                                        uint32_t b0, uint32_t b1) {
    asm volatile(
        "mma.sync.aligned.m16n8k16.row.col.f32.f16.f16.f32 "
        "{%0,%1,%2,%3}, {%4,%5,%6,%7}, {%8,%9}, {%0,%1,%2,%3};\n"
        : "+f"(d0), "+f"(d1), "+f"(d2), "+f"(d3)
        : "r"(a0), "r"(a1), "r"(a2), "r"(a3), "r"(b0), "r"(b1));
}

// ---------------------------------------------------------------------------
// Prep (proven): ||e||^2, packed fp16-hi fragments, per-block max norms.
// ---------------------------------------------------------------------------
__global__ void vq_prep(const float* __restrict__ emb) {
    const int t = blockIdx.x * blockDim.x + threadIdx.x;

    if (t < NGROUP * 2 * 32) {
        const int g = t >> 6;
        const int h = (t >> 5) & 1;
        const int l = t & 31;
        const int gid = l >> 2, tig = l & 3;
        const float* e = emb + (g * 8 + gid) * DIM;
        const int k0 = (2 * h) * 16 + tig * 2;
        const int k1 = (2 * h + 1) * 16 + tig * 2;
        uint4 u;
        u.x = pack_h2(__float2half_rn(e[k0] * ESCALE),     __float2half_rn(e[k0 + 1] * ESCALE));
        u.y = pack_h2(__float2half_rn(e[k0 + 8] * ESCALE), __float2half_rn(e[k0 + 9] * ESCALE));
        u.z = pack_h2(__float2half_rn(e[k1] * ESCALE),     __float2half_rn(e[k1 + 1] * ESCALE));
        u.w = pack_h2(__float2half_rn(e[k1 + 8] * ESCALE), __float2half_rn(e[k1 + 9] * ESCALE));
        g_b4[(g * 2 + h) * 32 + l] = u;
    }

    float nrm = 0.0f;
    if (t < K_EMB) {
        const float* e = emb + t * DIM;
        float s = 0.0f;
        #pragma unroll
        for (int j = 0; j < DIM; ++j)
            s = __fadd_rn(s, __fmul_rn(e[j], e[j]));
        g_se2[t] = s;
        nrm = sqrtf(s) * ESCALE;
    }
    if (blockIdx.x < 4) {
        __shared__ float rmx[8];
        float m = nrm;
        #pragma unroll
        for (int off = 16; off > 0; off >>= 1)
            m = fmaxf(m, __shfl_xor_sync(0xFFFFFFFFu, m, off));
        if ((threadIdx.x & 31) == 0) rmx[threadIdx.x >> 5] = m;
        __syncthreads();
        if (threadIdx.x == 0) {
            float mm = rmx[0];
            #pragma unroll
            for (int i = 1; i < 8; ++i) mm = fmaxf(mm, rmx[i]);
            g_maxNorm[blockIdx.x] = mm;
        }
    }
}

// ---------------------------------------------------------------------------
// Fused main (R11 structure, register-disciplined unrolls).
// ---------------------------------------------------------------------------
__global__ void __launch_bounds__(THREADS, 2)
vq_main(const float* __restrict__ z,
        const float* __restrict__ emb,
        float* __restrict__ out) {
    extern __shared__ __align__(16) char sm[];
    double* sRed   = reinterpret_cast<double*>(sm + SRED_OFF);
    int*    sCnt   = reinterpret_cast<int*>(sm + SCNT_OFF);
    int*    sLast  = reinterpret_cast<int*>(sm + SLAST_OFF);
    float*  sMaxE  = reinterpret_cast<float*>(sm + SMAXE_OFF);
    int*    sIdx   = reinterpret_cast<int*>(sm + SIDX_OFF);
    int*    sFq    = reinterpret_cast<int*>(sm + SFQ_OFF);
    int*    sFbi   = reinterpret_cast<int*>(sm + SFBI_OFF);
    float*  sFbest = reinterpret_cast<float*>(sm + SFBEST_OFF);
    float*  sSz    = reinterpret_cast<float*>(sm + SSZ_OFF);
    float*  sSe    = reinterpret_cast<float*>(sm + SSE_OFF);
    float*  sBuf   = reinterpret_cast<float*>(sm + SBUF_OFF);
    float*  sE     = reinterpret_cast<float*>(sm + SE_OFF);

    const int tid  = threadIdx.x;
    const int wid  = tid >> 5;
    const int lane = tid & 31;
    const int gid  = lane >> 2;
    const int tig  = lane & 3;

    if (tid == 0) {
        *sLast = 0;
        *sMaxE = fmaxf(fmaxf(g_maxNorm[0], g_maxNorm[1]),
                       fmaxf(g_maxNorm[2], g_maxNorm[3]));
    }
    #pragma unroll 4
    for (int i = tid; i < K_EMB; i += THREADS) sSe[i] = g_se2[i];

    double lsum = 0.0;

    for (int sub = 0; sub < SUBS; ++sub) {
        const int qb = (blockIdx.x + sub * GRID) * QB;
        __syncthreads();
        if (tid == 0) *sCnt = 0;

        // ---- stage z tile ----
        {
            const float4* src = reinterpret_cast<const float4*>(z + (size_t)qb * DIM);
            #pragma unroll 4
            for (int i = tid; i < QB * (DIM / 4); i += THREADS) {
                int row = i >> 4, c4 = i & 15;
                float4 v = __ldg(src + i);
                *reinterpret_cast<float4*>(&sBuf[row * PAD + 4 * c4]) = v;
            }
        }
        __syncthreads();

        // row norms (square-then-add, sequential) + flag init
        if (tid < QB) {
            const float* r = &sBuf[tid * PAD];
            float s = 0.0f;
            #pragma unroll
            for (int j = 0; j < DIM; ++j)
                s = __fadd_rn(s, __fmul_rn(r[j], r[j]));
            sSz[tid] = s;
            sFbest[tid] = 3.4e38f;
            sFbi[tid] = 0;
        }

        const int r0 = wid * 16 + gid;
        const int r1 = r0 + 8;

        // ---- screen ----
        {
            uint32_t aH[4][4];
            #pragma unroll
            for (int s = 0; s < 4; ++s) {
                const int k = s * 16 + tig * 2;
                aH[s][0] = pack_h2(__float2half_rn(sBuf[r0 * PAD + k]),
                                   __float2half_rn(sBuf[r0 * PAD + k + 1]));
                aH[s][1] = pack_h2(__float2half_rn(sBuf[r1 * PAD + k]),
                                   __float2half_rn(sBuf[r1 * PAD + k + 1]));
                aH[s][2] = pack_h2(__float2half_rn(sBuf[r0 * PAD + k + 8]),
                                   __float2half_rn(sBuf[r0 * PAD + k + 9]));
                aH[s][3] = pack_h2(__float2half_rn(sBuf[r1 * PAD + k + 8]),
                                   __float2half_rn(sBuf[r1 * PAD + k + 9]));
            }
            __syncthreads();
            const float sz0 = sSz[r0];
            const float sz1 = sSz[r1];

            float b0 = 3.4e38f, s0v = 3.4e38f; int i0 = 0;
            float b1 = 3.4e38f, s1v = 3.4e38f; int i1 = 0;

            #pragma unroll 2
            for (int g = 0; g < NGROUP; ++g) {
                const uint4 U0 = __ldg(&g_b4[(g * 2) * 32 + lane]);
                const uint4 U1 = __ldg(&g_b4[(g * 2 + 1) * 32 + lane]);
                float d0 = 0.f, d1 = 0.f, d2 = 0.f, d3 = 0.f;
                mma_f16(d0, d1, d2, d3, aH[0][0], aH[0][1], aH[0][2], aH[0][3], U0.x, U0.y);
                mma_f16(d0, d1, d2, d3, aH[1][0], aH[1][1], aH[1][2], aH[1][3], U0.z, U0.w);
                mma_f16(d0, d1, d2, d3, aH[2][0], aH[2][1], aH[2][2], aH[2][3], U1.x, U1.y);
                mma_f16(d0, d1, d2, d3, aH[3][0], aH[3][1], aH[3][2], aH[3][3], U1.z, U1.w);

                const int c0 = g * 8 + 2 * tig;
                const float se0 = sSe[c0], se1 = sSe[c0 + 1];
                const float q00 = sz0 - d0 * INV_2SCALE + se0;
                const float q01 = sz0 - d1 * INV_2SCALE + se1;
                const float q10 = sz1 - d2 * INV_2SCALE + se0;
                const float q11 = sz1 - d3 * INV_2SCALE + se1;

                if (q00 < b0) { s0v = b0; b0 = q00; i0 = c0; }     else if (q00 < s0v) s0v = q00;
                if (q01 < b0) { s0v = b0; b0 = q01; i0 = c0 + 1; } else if (q01 < s0v) s0v = q01;
                if (q10 < b1) { s1v = b1; b1 = q10; i1 = c0; }     else if (q10 < s1v) s1v = q10;
                if (q11 < b1) { s1v = b1; b1 = q11; i1 = c0 + 1; } else if (q11 < s1v) s1v = q11;
            }

            #pragma unroll
            for (int off = 1; off <= 2; off <<= 1) {
                float ob = __shfl_xor_sync(0xFFFFFFFFu, b0, off);
                int   oi = __shfl_xor_sync(0xFFFFFFFFu, i0, off);
                float os = __shfl_xor_sync(0xFFFFFFFFu, s0v, off);
                if (ob < b0) { s0v = fminf(b0, os); b0 = ob; i0 = oi; }
                else         { s0v = fminf(s0v, ob); }
                float ob1 = __shfl_xor_sync(0xFFFFFFFFu, b1, off);
                int   oi1 = __shfl_xor_sync(0xFFFFFFFFu, i1, off);
                float os1 = __shfl_xor_sync(0xFFFFFFFFu, s1v, off);
                if (ob1 < b1) { s1v = fminf(b1, os1); b1 = ob1; i1 = oi1; }
                else          { s1v = fminf(s1v, ob1); }
            }

            if (tig == 0) {
                const float mE = *sMaxE;
                sIdx[r0] = i0;
                sIdx[r1] = i1;
                const float m0 = sqrtf(sz0) * mE * 4.0e-6f + 1.2e-4f;
                const float m1 = sqrtf(sz1) * mE * 4.0e-6f + 1.2e-4f;
                if (s0v - b0 <= m0) { int p = atomicAdd(sCnt, 1); sFq[p] = r0; }
                if (s1v - b1 <= m1) { int p = atomicAdd(sCnt, 1); sFq[p] = r1; }
            }
        }
        __syncthreads();

        // ---- rescue via smem-staged codebook chunks ----
        const int cnt = *sCnt;
        if (cnt > 0) {
            #pragma unroll 1
            for (int ch = 0; ch < K_EMB / QB; ++ch) {
                __syncthreads();
                const float4* src = reinterpret_cast<const float4*>(emb + (size_t)ch * QB * DIM);
                #pragma unroll 4
                for (int i = tid; i < QB * (DIM / 4); i += THREADS) {
                    int row = i >> 4, c4 = i & 15;
                    float4 v = __ldg(src + i);
                    *reinterpret_cast<float4*>(&sE[row * PAD + 4 * c4]) = v;
                }
                __syncthreads();

                #pragma unroll 1
                for (int f = wid; f < cnt; f += THREADS / 32) {
                    const int q = sFq[f];
                    const float szq = sSz[q];
                    const float4* zq4 = reinterpret_cast<const float4*>(&sBuf[q * PAD]);
                    float best = 3.4e38f; int bi = 0;
                    #pragma unroll 1
                    for (int k = 0; k < 4; ++k) {
                        const int cl = k * 32 + lane;
                        const float4* e4 = reinterpret_cast<const float4*>(&sE[cl * PAD]);
                        float a0 = 0.f, a1 = 0.f, a2 = 0.f, a3 = 0.f;
                        #pragma unroll 4
                        for (int j = 0; j < DIM / 4; ++j) {
                            float4 e = e4[j];
                            float4 zv = zq4[j];
                            a0 = fmaf(zv.x, e.x, a0);
                            a1 = fmaf(zv.y, e.y, a1);
                            a2 = fmaf(zv.z, e.z, a2);
                            a3 = fmaf(zv.w, e.w, a3);
                        }
                        float dot = __fadd_rn(__fadd_rn(a0, a1), __fadd_rn(a2, a3));
                        const int c = ch * QB + cl;
                        float d2 = __fadd_rn(__fsub_rn(szq, __fmul_rn(2.0f, dot)), sSe[c]);
                        if (d2 < best) { best = d2; bi = c; }
                    }
                    #pragma unroll
                    for (int off = 16; off > 0; off >>= 1) {
                        float ov = __shfl_down_sync(0xFFFFFFFFu, best, off);
                        int   oi = __shfl_down_sync(0xFFFFFFFFu, bi, off);
                        if (ov < best || (ov == best && oi < bi)) { best = ov; bi = oi; }
                    }
                    if (lane == 0) {
                        if (best < sFbest[f] || (best == sFbest[f] && bi < sFbi[f])) {
                            sFbest[f] = best; sFbi[f] = bi;
                        }
                    }
                }
            }
            __syncthreads();
            if (tid < cnt) sIdx[sFq[tid]] = sFbi[tid];
        }
        __syncthreads();

        // ---- cooperative gather of selected code rows into sE ----
        #pragma unroll 1
        for (int i = tid; i < QB * (DIM / 4); i += THREADS) {
            int row = i >> 4, c4 = i & 15;
            const float4* src = reinterpret_cast<const float4*>(emb + (size_t)sIdx[row] * DIM);
            *reinterpret_cast<float4*>(&sE[row * PAD + 4 * c4]) = __ldg(src + c4);
        }
        __syncthreads();

        // ---- outputs: STE, idx, loss partial (register-limited unroll) ----
        if (tid < QB) {
            const int n = qb + tid;
            const int bidx = sIdx[tid];
            const int w = n & 31;
            const int h = (n >> 5) & 31;
            const int b = n >> 10;
            const size_t obase = (size_t)b * 65536 + (size_t)h * 32 + w;

            const float4* zr4 = reinterpret_cast<const float4*>(&sBuf[tid * PAD]);
            const float4* er4 = reinterpret_cast<const float4*>(&sE[tid * PAD]);
            #pragma unroll 2
            for (int j = 0; j < DIM / 4; ++j) {
                float4 zv = zr4[j];
                float4 ev = er4[j];
                float zq[4] = {zv.x, zv.y, zv.z, zv.w};
                float eq[4] = {ev.x, ev.y, ev.z, ev.w};
                #pragma unroll
                for (int u = 0; u < 4; ++u) {
                    const int d = 4 * j + u;
                    float diff = __fsub_rn(eq[u], zq[u]);
                    out[obase + (size_t)d * 1024] = __fadd_rn(zq[u], diff);  // STE
                    lsum += (double)diff * (double)diff;
                }
            }
            out[OUT_IDX_OFF + (size_t)n] = (float)bidx;
        }
    }

    // ---- loss reduction + last-block finalize ----
    #pragma unroll
    for (int off = 16; off > 0; off >>= 1)
        lsum += __shfl_down_sync(0xFFFFFFFFu, lsum, off);
    if (lane == 0) sRed[wid] = lsum;
    __syncthreads();
    if (tid == 0) {
        double v = 0.0;
        #pragma unroll
        for (int i = 0; i < THREADS / 32; ++i) v += sRed[i];
        g_partial[blockIdx.x] = v;
        __threadfence();
        unsigned old = atomicAdd(&g_done, 1u);
        if ((old & (GRID - 1)) == (GRID - 1)) *sLast = 1;
    }
    __syncthreads();

    if (*sLast && wid == 0) {
        __threadfence();
        double v = 0.0;
        #pragma unroll
        for (int i = 0; i < GRID / 32; ++i)
            v += g_partial[lane + i * 32];
        #pragma unroll
        for (int off = 16; off > 0; off >>= 1)
            v += __shfl_down_sync(0xFFFFFFFFu, v, off);
        if (lane == 0) {
            double mean = v / (double)OUT_QV_ELEMS;
            out[OUT_LOSS_OFF] = (float)(mean * 0.25 + mean * 1.0);
        }
    }
}

extern "C" void kernel_launch(void* const* d_in, const int* in_sizes, int n_in,
                              void* d_out, int out_size) {
    const float* z   = (const float*)d_in[0];
    const float* emb = (const float*)d_in[1];
    float* out = (float*)d_out;

    cudaFuncSetAttribute(vq_main, cudaFuncAttributeMaxDynamicSharedMemorySize, SMEM_MAIN);

    vq_prep<<<(NGROUP * 2 * 32 + 255) / 256, 256>>>(emb);
    vq_main<<<GRID, THREADS, SMEM_MAIN>>>(z, emb, out);
}

// round 14
// speedup vs baseline: 1.0137x; 1.0137x over previous
#include <cuda_runtime.h>
#include <cuda_fp16.h>
#include <cstdint>

// Shapes
#define N_Q    65536
#define DIM    64
#define K_EMB  1024
#define QB     128
#define THREADS 256
#define NBLOCKS (N_Q / QB)    // 512
#define NGROUP 128
#define PAD    68

#define ESCALE      1024.0f
#define INV_2SCALE  (1.0f / 512.0f)

#define OUT_QV_ELEMS  (64ULL * 64ULL * 32ULL * 32ULL)
#define OUT_IDX_OFF   4194304ULL
#define OUT_LOSS_OFF  4259840ULL

// ---- dynamic smem layout (byte offsets) ----
#define SRED_OFF    0        // double[8]
#define SCNT_OFF    64
#define SLAST_OFF   68
#define SMAXE_OFF   72
#define SIDX_OFF    80       // int[128]
#define SFQ_OFF     592      // int[128]
#define SFBI_OFF    1104     // int[128]
#define SFBEST_OFF  1616     // float[128]
#define SSZ_OFF     2128     // float[128]
#define SSE_OFF     2688     // float[1024]
#define SBUF_OFF    6784     // float[128*68]  z tile (padded)
#define SB_OFF      41600    // 32KB: B-frag staging / rescue chunks / gather
#define SMEM_MAIN   74368

// device scratch (zero-initialized at load)
__device__ float    g_se2[K_EMB];
__device__ float    g_maxNorm[4];
__device__ uint4    g_b4[NGROUP * 2 * 32];
__device__ double   g_partial[NBLOCKS];
__device__ unsigned g_done;                  // monotonic; 2^32 % 512 == 0

__device__ __forceinline__ uint32_t pack_h2(__half lo, __half hi) {
    __half2 h = __halves2half2(lo, hi);
    return *reinterpret_cast<uint32_t*>(&h);
}

__device__ __forceinline__ void mma_f16(float& d0, float& d1, float& d2, float& d3,
                                        uint32_t a0, uint32_t a1, uint32_t a2, uint32_t a3,
                                        uint32_t b0, uint32_t b1) {
    asm volatile(
        "mma.sync.aligned.m16n8k16.row.col.f32.f16.f16.f32 "
        "{%0,%1,%2,%3}, {%4,%5,%6,%7}, {%8,%9}, {%0,%1,%2,%3};\n"
        : "+f"(d0), "+f"(d1), "+f"(d2), "+f"(d3)
        : "r"(a0), "r"(a1), "r"(a2), "r"(a3), "r"(b0), "r"(b1));
}

// ---------------------------------------------------------------------------
// Prep (proven, unchanged).
// ---------------------------------------------------------------------------
__global__ void vq_prep(const float* __restrict__ emb) {
    const int t = blockIdx.x * blockDim.x + threadIdx.x;

    if (t < NGROUP * 2 * 32) {
        const int g = t >> 6;
        const int h = (t >> 5) & 1;
        const int l = t & 31;
        const int gid = l >> 2, tig = l & 3;
        const float* e = emb + (g * 8 + gid) * DIM;
        const int k0 = (2 * h) * 16 + tig * 2;
        const int k1 = (2 * h + 1) * 16 + tig * 2;
        uint4 u;
        u.x = pack_h2(__float2half_rn(e[k0] * ESCALE),     __float2half_rn(e[k0 + 1] * ESCALE));
        u.y = pack_h2(__float2half_rn(e[k0 + 8] * ESCALE), __float2half_rn(e[k0 + 9] * ESCALE));
        u.z = pack_h2(__float2half_rn(e[k1] * ESCALE),     __float2half_rn(e[k1 + 1] * ESCALE));
        u.w = pack_h2(__float2half_rn(e[k1 + 8] * ESCALE), __float2half_rn(e[k1 + 9] * ESCALE));
        g_b4[(g * 2 + h) * 32 + l] = u;
    }

    float nrm = 0.0f;
    if (t < K_EMB) {
        const float* e = emb + t * DIM;
        float s = 0.0f;
        #pragma unroll
        for (int j = 0; j < DIM; ++j)
            s = __fadd_rn(s, __fmul_rn(e[j], e[j]));
        g_se2[t] = s;
        nrm = sqrtf(s) * ESCALE;
    }
    if (blockIdx.x < 4) {
        __shared__ float rmx[8];
        float m = nrm;
        #pragma unroll
        for (int off = 16; off > 0; off >>= 1)
            m = fmaxf(m, __shfl_xor_sync(0xFFFFFFFFu, m, off));
        if ((threadIdx.x & 31) == 0) rmx[threadIdx.x >> 5] = m;
        __syncthreads();
        if (threadIdx.x == 0) {
            float mm = rmx[0];
            #pragma unroll
            for (int i = 1; i < 8; ++i) mm = fmaxf(mm, rmx[i]);
            g_maxNorm[blockIdx.x] = mm;
        }
    }
}

// ---------------------------------------------------------------------------
// Fused main: smem-staged screen, smem-chunk rescue, swizzled gather.
// ---------------------------------------------------------------------------
__global__ void __launch_bounds__(THREADS, 3)
vq_main(const float* __restrict__ z,
        const float* __restrict__ emb,
        float* __restrict__ out) {
    extern __shared__ __align__(16) char sm[];
    double* sRed   = reinterpret_cast<double*>(sm + SRED_OFF);
    int*    sCnt   = reinterpret_cast<int*>(sm + SCNT_OFF);
    int*    sLast  = reinterpret_cast<int*>(sm + SLAST_OFF);
    float*  sMaxE  = reinterpret_cast<float*>(sm + SMAXE_OFF);
    int*    sIdx   = reinterpret_cast<int*>(sm + SIDX_OFF);
    int*    sFq    = reinterpret_cast<int*>(sm + SFQ_OFF);
    int*    sFbi   = reinterpret_cast<int*>(sm + SFBI_OFF);
    float*  sFbest = reinterpret_cast<float*>(sm + SFBEST_OFF);
    float*  sSz    = reinterpret_cast<float*>(sm + SSZ_OFF);
    float*  sSe    = reinterpret_cast<float*>(sm + SSE_OFF);
    float*  sBuf   = reinterpret_cast<float*>(sm + SBUF_OFF);
    uint4*  sB4    = reinterpret_cast<uint4*>(sm + SB_OFF);     // frag staging
    float4* sG4    = reinterpret_cast<float4*>(sm + SB_OFF);    // rescue/gather

    const int tid  = threadIdx.x;
    const int wid  = tid >> 5;
    const int lane = tid & 31;
    const int gid  = lane >> 2;
    const int tig  = lane & 3;
    const int qb   = blockIdx.x * QB;

    if (tid == 0) {
        *sCnt = 0; *sLast = 0;
        *sMaxE = fmaxf(fmaxf(g_maxNorm[0], g_maxNorm[1]),
                       fmaxf(g_maxNorm[2], g_maxNorm[3]));
    }
    #pragma unroll 4
    for (int i = tid; i < K_EMB; i += THREADS) sSe[i] = g_se2[i];

    // ---- stage z tile ----
    {
        const float4* src = reinterpret_cast<const float4*>(z + (size_t)qb * DIM);
        #pragma unroll 4
        for (int i = tid; i < QB * (DIM / 4); i += THREADS) {
            int row = i >> 4, c4 = i & 15;
            float4 v = __ldg(src + i);
            *reinterpret_cast<float4*>(&sBuf[row * PAD + 4 * c4]) = v;
        }
    }
    __syncthreads();

    // row norms + flag init
    if (tid < QB) {
        const float* r = &sBuf[tid * PAD];
        float s = 0.0f;
        #pragma unroll
        for (int j = 0; j < DIM; ++j)
            s = __fadd_rn(s, __fmul_rn(r[j], r[j]));
        sSz[tid] = s;
        sFbest[tid] = 3.4e38f;
        sFbi[tid] = 0;
    }

    const int r0 = wid * 16 + gid;
    const int r1 = r0 + 8;

    // ---- screen: A frags, then 4 staged B chunks of 32 groups ----
    {
        uint32_t aH[4][4];
        #pragma unroll
        for (int s = 0; s < 4; ++s) {
            const int k = s * 16 + tig * 2;
            aH[s][0] = pack_h2(__float2half_rn(sBuf[r0 * PAD + k]),
                               __float2half_rn(sBuf[r0 * PAD + k + 1]));
            aH[s][1] = pack_h2(__float2half_rn(sBuf[r1 * PAD + k]),
                               __float2half_rn(sBuf[r1 * PAD + k + 1]));
            aH[s][2] = pack_h2(__float2half_rn(sBuf[r0 * PAD + k + 8]),
                               __float2half_rn(sBuf[r0 * PAD + k + 9]));
            aH[s][3] = pack_h2(__float2half_rn(sBuf[r1 * PAD + k + 8]),
                               __float2half_rn(sBuf[r1 * PAD + k + 9]));
        }
        __syncthreads();
        const float sz0 = sSz[r0];
        const float sz1 = sSz[r1];

        float b0 = 3.4e38f, s0v = 3.4e38f; int i0 = 0;
        float b1 = 3.4e38f, s1v = 3.4e38f; int i1 = 0;

        #pragma unroll 1
        for (int c = 0; c < 4; ++c) {
            // stage 32 groups of fragments: 2048 uint4, coalesced
            {
                const uint4* src = g_b4 + c * 2048;
                #pragma unroll
                for (int i = tid; i < 2048; i += THREADS)
                    sB4[i] = __ldg(src + i);
            }
            __syncthreads();

            #pragma unroll 2
            for (int gc = 0; gc < 32; ++gc) {
                const uint4 U0 = sB4[(gc * 2) * 32 + lane];
                const uint4 U1 = sB4[(gc * 2 + 1) * 32 + lane];
                float d0 = 0.f, d1 = 0.f, d2 = 0.f, d3 = 0.f;
                mma_f16(d0, d1, d2, d3, aH[0][0], aH[0][1], aH[0][2], aH[0][3], U0.x, U0.y);
                mma_f16(d0, d1, d2, d3, aH[1][0], aH[1][1], aH[1][2], aH[1][3], U0.z, U0.w);
                mma_f16(d0, d1, d2, d3, aH[2][0], aH[2][1], aH[2][2], aH[2][3], U1.x, U1.y);
                mma_f16(d0, d1, d2, d3, aH[3][0], aH[3][1], aH[3][2], aH[3][3], U1.z, U1.w);

                const int c0 = (c * 32 + gc) * 8 + 2 * tig;
                const float se0 = sSe[c0], se1 = sSe[c0 + 1];
                const float q00 = sz0 - d0 * INV_2SCALE + se0;
                const float q01 = sz0 - d1 * INV_2SCALE + se1;
                const float q10 = sz1 - d2 * INV_2SCALE + se0;
                const float q11 = sz1 - d3 * INV_2SCALE + se1;

                if (q00 < b0) { s0v = b0; b0 = q00; i0 = c0; }     else if (q00 < s0v) s0v = q00;
                if (q01 < b0) { s0v = b0; b0 = q01; i0 = c0 + 1; } else if (q01 < s0v) s0v = q01;
                if (q10 < b1) { s1v = b1; b1 = q10; i1 = c0; }     else if (q10 < s1v) s1v = q10;
                if (q11 < b1) { s1v = b1; b1 = q11; i1 = c0 + 1; } else if (q11 < s1v) s1v = q11;
            }
            __syncthreads();
        }

        #pragma unroll
        for (int off = 1; off <= 2; off <<= 1) {
            float ob = __shfl_xor_sync(0xFFFFFFFFu, b0, off);
            int   oi = __shfl_xor_sync(0xFFFFFFFFu, i0, off);
            float os = __shfl_xor_sync(0xFFFFFFFFu, s0v, off);
            if (ob < b0) { s0v = fminf(b0, os); b0 = ob; i0 = oi; }
            else         { s0v = fminf(s0v, ob); }
            float ob1 = __shfl_xor_sync(0xFFFFFFFFu, b1, off);
            int   oi1 = __shfl_xor_sync(0xFFFFFFFFu, i1, off);
            float os1 = __shfl_xor_sync(0xFFFFFFFFu, s1v, off);
            if (ob1 < b1) { s1v = fminf(b1, os1); b1 = ob1; i1 = oi1; }
            else          { s1v = fminf(s1v, ob1); }
        }

        if (tig == 0) {
            const float mE = *sMaxE;
            sIdx[r0] = i0;
            sIdx[r1] = i1;
            const float m0 = sqrtf(sSz[r0]) * mE * 4.0e-6f + 1.2e-4f;
            const float m1 = sqrtf(sSz[r1]) * mE * 4.0e-6f + 1.2e-4f;
            if (s0v - b0 <= m0) { int p = atomicAdd(sCnt, 1); sFq[p] = r0; }
            if (s1v - b1 <= m1) { int p = atomicAdd(sCnt, 1); sFq[p] = r1; }
        }
    }
    __syncthreads();

    // ---- rescue: 8 smem chunks of 128 codes (rotation-swizzled, unpadded) ----
    const int cnt = *sCnt;
    if (cnt > 0) {
        #pragma unroll 1
        for (int ch = 0; ch < K_EMB / 128; ++ch) {
            __syncthreads();
            {
                const float4* src = reinterpret_cast<const float4*>(emb + (size_t)ch * 128 * DIM);
                #pragma unroll 4
                for (int i = tid; i < 128 * (DIM / 4); i += THREADS) {
                    int row = i >> 4, c4 = i & 15;
                    sG4[row * 16 + ((c4 + row) & 15)] = __ldg(src + i);
                }
            }
            __syncthreads();

            #pragma unroll 1
            for (int f = wid; f < cnt; f += THREADS / 32) {
                const int q = sFq[f];
                const float szq = sSz[q];
                const float4* zq4 = reinterpret_cast<const float4*>(&sBuf[q * PAD]);
                float best = 3.4e38f; int bi = 0;
                #pragma unroll 1
                for (int k = 0; k < 4; ++k) {
                    const int cl = k * 32 + lane;
                    float a0 = 0.f, a1 = 0.f, a2 = 0.f, a3 = 0.f;
                    #pragma unroll 4
                    for (int j = 0; j < DIM / 4; ++j) {
                        // slot (j+cl)&15 holds ELEMENT j of row cl  ->  pair with zq4[j]
                        float4 e = sG4[cl * 16 + ((j + cl) & 15)];
                        float4 zv = zq4[j];                 // broadcast LDS.128
                        a0 = fmaf(zv.x, e.x, a0);
                        a1 = fmaf(zv.y, e.y, a1);
                        a2 = fmaf(zv.z, e.z, a2);
                        a3 = fmaf(zv.w, e.w, a3);
                    }
                    float dot = __fadd_rn(__fadd_rn(a0, a1), __fadd_rn(a2, a3));
                    const int c = ch * 128 + cl;
                    float d2 = __fadd_rn(__fsub_rn(szq, __fmul_rn(2.0f, dot)), sSe[c]);
                    if (d2 < best) { best = d2; bi = c; }
                }
                #pragma unroll
                for (int off = 16; off > 0; off >>= 1) {
                    float ov = __shfl_down_sync(0xFFFFFFFFu, best, off);
                    int   oi = __shfl_down_sync(0xFFFFFFFFu, bi, off);
                    if (ov < best || (ov == best && oi < bi)) { best = ov; bi = oi; }
                }
                if (lane == 0) {
                    if (best < sFbest[f] || (best == sFbest[f] && bi < sFbi[f])) {
                        sFbest[f] = best; sFbi[f] = bi;
                    }
                }
            }
        }
        __syncthreads();
        if (tid < cnt) sIdx[sFq[tid]] = sFbi[tid];
    }
    __syncthreads();

    // ---- gather selected code rows into sG4 (coalesced, rotation-swizzled) ----
    #pragma unroll 2
    for (int i = tid; i < QB * (DIM / 4); i += THREADS) {
        int row = i >> 4, c4 = i & 15;
        const float4* src = reinterpret_cast<const float4*>(emb + (size_t)sIdx[row] * DIM);
        sG4[row * 16 + ((c4 + row) & 15)] = __ldg(src + c4);
    }
    __syncthreads();

    // ---- outputs: STE, idx, loss partial ----
    double lsum = 0.0;
    if (tid < QB) {
        const int n = qb + tid;
        const int bidx = sIdx[tid];
        const int w = n & 31;
        const int h = (n >> 5) & 31;
        const int b = n >> 10;
        const size_t obase = (size_t)b * 65536 + (size_t)h * 32 + w;

        const float4* zr4 = reinterpret_cast<const float4*>(&sBuf[tid * PAD]);
        #pragma unroll 2
        for (int j = 0; j < DIM / 4; ++j) {
            float4 zv = zr4[j];
            float4 ev = sG4[tid * 16 + ((j + tid) & 15)];   // element j of row tid
            float zq[4] = {zv.x, zv.y, zv.z, zv.w};
            float eq[4] = {ev.x, ev.y, ev.z, ev.w};
            #pragma unroll
            for (int u = 0; u < 4; ++u) {
                const int d = 4 * j + u;
                float diff = __fsub_rn(eq[u], zq[u]);
                out[obase + (size_t)d * 1024] = __fadd_rn(zq[u], diff);  // STE
                lsum += (double)diff * (double)diff;
            }
        }
        out[OUT_IDX_OFF + (size_t)n] = (float)bidx;
    }

    // ---- loss reduction + last-block finalize ----
    #pragma unroll
    for (int off = 16; off > 0; off >>= 1)
        lsum += __shfl_down_sync(0xFFFFFFFFu, lsum, off);
    if (lane == 0) sRed[wid] = lsum;
    __syncthreads();
    if (tid == 0) {
        double v = 0.0;
        #pragma unroll
        for (int i = 0; i < THREADS / 32; ++i) v += sRed[i];
        g_partial[blockIdx.x] = v;
        __threadfence();
        unsigned old = atomicAdd(&g_done, 1u);
        if ((old & (NBLOCKS - 1)) == (NBLOCKS - 1)) *sLast = 1;
    }
    __syncthreads();

    if (*sLast && wid == 0) {
        __threadfence();
        double v = 0.0;
        #pragma unroll
        for (int i = 0; i < NBLOCKS / 32; ++i)
            v += g_partial[lane + i * 32];
        #pragma unroll
        for (int off = 16; off > 0; off >>= 1)
            v += __shfl_down_sync(0xFFFFFFFFu, v, off);
        if (lane == 0) {
            double mean = v / (double)OUT_QV_ELEMS;
            out[OUT_LOSS_OFF] = (float)(mean * 0.25 + mean * 1.0);
        }
    }
}

extern "C" void kernel_launch(void* const* d_in, const int* in_sizes, int n_in,
                              void* d_out, int out_size) {
    const float* z   = (const float*)d_in[0];
    const float* emb = (const float*)d_in[1];
    float* out = (float*)d_out;

    cudaFuncSetAttribute(vq_main, cudaFuncAttributeMaxDynamicSharedMemorySize, SMEM_MAIN);

    vq_prep<<<(NGROUP * 2 * 32 + 255) / 256, 256>>>(emb);
    vq_main<<<NBLOCKS, THREADS, SMEM_MAIN>>>(z, emb, out);
}

// round 15
// speedup vs baseline: 1.5015x; 1.4811x over previous
#include <cuda_runtime.h>
#include <cuda_fp16.h>
#include <cstdint>

// Shapes
#define N_Q    65536
#define DIM    64
#define K_EMB  1024
#define QB     128
#define THREADS 256
#define NBLOCKS (N_Q / QB)    // 512
#define NGROUP 128
#define PAD    68

#define ESCALE      1024.0f
#define INV_2SCALE  (1.0f / 512.0f)

#define OUT_QV_ELEMS  (64ULL * 64ULL * 32ULL * 32ULL)
#define OUT_IDX_OFF   4194304ULL
#define OUT_LOSS_OFF  4259840ULL

// ---- dynamic smem layout (byte offsets, 16B-aligned blocks) ----
#define SRED_OFF    0        // double[8]
#define SLAST_OFF   64       // int
#define SIDX_OFF    80       // int[128]
#define SSZ_OFF     592      // float[128]
#define SSE_OFF     1104     // float[1024]
#define SBUF_OFF    5200     // float[128*68]  z tile (padded)
#define SG_OFF      40016    // float4[128*16] gather buffer (32KB)
#define SMEM_MAIN   72784

// device scratch (zero-initialized at load)
__device__ float    g_se2[K_EMB];
__device__ uint4    g_bh4[NGROUP * 2 * 32];   // hi  frags: (g*2+h)*32+lane
__device__ uint4    g_bm4[NGROUP * 2 * 32];   // mid frags
__device__ double   g_partial[NBLOCKS];
__device__ unsigned g_done;                   // monotonic; 2^32 % 512 == 0

__device__ __forceinline__ uint32_t pack_h2(__half lo, __half hi) {
    __half2 h = __halves2half2(lo, hi);
    return *reinterpret_cast<uint32_t*>(&h);
}

__device__ __forceinline__ void mma_f16(float& d0, float& d1, float& d2, float& d3,
                                        uint32_t a0, uint32_t a1, uint32_t a2, uint32_t a3,
                                        uint32_t b0, uint32_t b1) {
    asm volatile(
        "mma.sync.aligned.m16n8k16.row.col.f32.f16.f16.f32 "
        "{%0,%1,%2,%3}, {%4,%5,%6,%7}, {%8,%9}, {%0,%1,%2,%3};\n"
        : "+f"(d0), "+f"(d1), "+f"(d2), "+f"(d3)
        : "r"(a0), "r"(a1), "r"(a2), "r"(a3), "r"(b0), "r"(b1));
}

// ---------------------------------------------------------------------------
// Prep: ||e||^2 + packed fp16 hi/mid B fragments (uint4 layout).
// ---------------------------------------------------------------------------
__global__ void vq_prep(const float* __restrict__ emb) {
    const int t = blockIdx.x * blockDim.x + threadIdx.x;

    if (t < NGROUP * 2 * 32) {
        const int g = t >> 6;
        const int h = (t >> 5) & 1;
        const int l = t & 31;
        const int gid = l >> 2, tig = l & 3;
        const float* e = emb + (g * 8 + gid) * DIM;
        const int k0 = (2 * h) * 16 + tig * 2;
        const int k1 = (2 * h + 1) * 16 + tig * 2;

        float v[8] = { e[k0] * ESCALE, e[k0 + 1] * ESCALE,
                       e[k0 + 8] * ESCALE, e[k0 + 9] * ESCALE,
                       e[k1] * ESCALE, e[k1 + 1] * ESCALE,
                       e[k1 + 8] * ESCALE, e[k1 + 9] * ESCALE };
        __half hh[8], mm[8];
        #pragma unroll
        for (int i = 0; i < 8; ++i) {
            hh[i] = __float2half_rn(v[i]);
            mm[i] = __float2half_rn(__fsub_rn(v[i], __half2float(hh[i])));
        }
        uint4 uh, um;
        uh.x = pack_h2(hh[0], hh[1]); uh.y = pack_h2(hh[2], hh[3]);
        uh.z = pack_h2(hh[4], hh[5]); uh.w = pack_h2(hh[6], hh[7]);
        um.x = pack_h2(mm[0], mm[1]); um.y = pack_h2(mm[2], mm[3]);
        um.z = pack_h2(mm[4], mm[5]); um.w = pack_h2(mm[6], mm[7]);
        g_bh4[t] = uh;
        g_bm4[t] = um;
    }

    if (t < K_EMB) {
        const float* e = emb + t * DIM;
        float s = 0.0f;
        #pragma unroll
        for (int j = 0; j < DIM; ++j)
            s = __fadd_rn(s, __fmul_rn(e[j], e[j]));
        g_se2[t] = s;
    }
}

// ---------------------------------------------------------------------------
// Main: R5 core (12-MMA 3-term split, exact rounding, best-only argmin)
// + coalesced swizzled gather epilogue + last-block loss finalize.
// ---------------------------------------------------------------------------
__global__ void __launch_bounds__(THREADS, 3)
vq_main(const float* __restrict__ z,
        const float* __restrict__ emb,
        float* __restrict__ out) {
    extern __shared__ __align__(16) char sm[];
    double* sRed  = reinterpret_cast<double*>(sm + SRED_OFF);
    int*    sLast = reinterpret_cast<int*>(sm + SLAST_OFF);
    int*    sIdx  = reinterpret_cast<int*>(sm + SIDX_OFF);
    float*  sSz   = reinterpret_cast<float*>(sm + SSZ_OFF);
    float*  sSe   = reinterpret_cast<float*>(sm + SSE_OFF);
    float*  sBuf  = reinterpret_cast<float*>(sm + SBUF_OFF);
    float4* sG4   = reinterpret_cast<float4*>(sm + SG_OFF);

    const int tid  = threadIdx.x;
    const int wid  = tid >> 5;
    const int lane = tid & 31;
    const int gid  = lane >> 2;
    const int tig  = lane & 3;
    const int qb   = blockIdx.x * QB;

    if (tid == 0) *sLast = 0;

    // ---- stage z tile + se ----
    {
        const float4* src = reinterpret_cast<const float4*>(z + (size_t)qb * DIM);
        #pragma unroll 4
        for (int i = tid; i < QB * (DIM / 4); i += THREADS) {
            int row = i >> 4, c4 = i & 15;
            float4 v = __ldg(src + i);
            *reinterpret_cast<float4*>(&sBuf[row * PAD + 4 * c4]) = v;
        }
        #pragma unroll 4
        for (int i = tid; i < K_EMB; i += THREADS) sSe[i] = g_se2[i];
    }
    __syncthreads();

    // row norms (square-then-add, sequential; reference style)
    if (tid < QB) {
        const float* r = &sBuf[tid * PAD];
        float s = 0.0f;
        #pragma unroll
        for (int j = 0; j < DIM; ++j)
            s = __fadd_rn(s, __fmul_rn(r[j], r[j]));
        sSz[tid] = s;
    }

    // ---- A fragments (fp16 hi & mid splits), rows r0=wid*16+gid, r1=r0+8 ----
    uint32_t aH[4][4], aM[4][4];
    const int r0 = wid * 16 + gid;
    const int r1 = r0 + 8;
    __syncthreads();
    #pragma unroll
    for (int s = 0; s < 4; ++s) {
        const int k = s * 16 + tig * 2;
        const float v[4][2] = {
            { sBuf[r0 * PAD + k],     sBuf[r0 * PAD + k + 1] },
            { sBuf[r1 * PAD + k],     sBuf[r1 * PAD + k + 1] },
            { sBuf[r0 * PAD + k + 8], sBuf[r0 * PAD + k + 9] },
            { sBuf[r1 * PAD + k + 8], sBuf[r1 * PAD + k + 9] },
        };
        #pragma unroll
        for (int q = 0; q < 4; ++q) {
            __half h0 = __float2half_rn(v[q][0]);
            __half h1 = __float2half_rn(v[q][1]);
            __half m0 = __float2half_rn(__fsub_rn(v[q][0], __half2float(h0)));
            __half m1 = __float2half_rn(__fsub_rn(v[q][1], __half2float(h1)));
            aH[s][q] = pack_h2(h0, h1);
            aM[s][q] = pack_h2(m0, m1);
        }
    }
    const float sz0 = sSz[r0];
    const float sz1 = sSz[r1];

    float best0 = 3.4e38f, best1 = 3.4e38f;
    int   idx0  = 0,       idx1  = 0;

    // ---- main loop: 128 n-groups, 12 MMA each (hh x4, hm x4, mh x4) ----
    #pragma unroll 2
    for (int g = 0; g < NGROUP; ++g) {
        const uint4 U0h = __ldg(&g_bh4[(g * 2) * 32 + lane]);
        const uint4 U1h = __ldg(&g_bh4[(g * 2 + 1) * 32 + lane]);
        const uint4 U0m = __ldg(&g_bm4[(g * 2) * 32 + lane]);
        const uint4 U1m = __ldg(&g_bm4[(g * 2 + 1) * 32 + lane]);

        float d0 = 0.f, d1 = 0.f, d2 = 0.f, d3 = 0.f;
        // hh
        mma_f16(d0, d1, d2, d3, aH[0][0], aH[0][1], aH[0][2], aH[0][3], U0h.x, U0h.y);
        mma_f16(d0, d1, d2, d3, aH[1][0], aH[1][1], aH[1][2], aH[1][3], U0h.z, U0h.w);
        mma_f16(d0, d1, d2, d3, aH[2][0], aH[2][1], aH[2][2], aH[2][3], U1h.x, U1h.y);
        mma_f16(d0, d1, d2, d3, aH[3][0], aH[3][1], aH[3][2], aH[3][3], U1h.z, U1h.w);
        // hm
        mma_f16(d0, d1, d2, d3, aH[0][0], aH[0][1], aH[0][2], aH[0][3], U0m.x, U0m.y);
        mma_f16(d0, d1, d2, d3, aH[1][0], aH[1][1], aH[1][2], aH[1][3], U0m.z, U0m.w);
        mma_f16(d0, d1, d2, d3, aH[2][0], aH[2][1], aH[2][2], aH[2][3], U1m.x, U1m.y);
        mma_f16(d0, d1, d2, d3, aH[3][0], aH[3][1], aH[3][2], aH[3][3], U1m.z, U1m.w);
        // mh
        mma_f16(d0, d1, d2, d3, aM[0][0], aM[0][1], aM[0][2], aM[0][3], U0h.x, U0h.y);
        mma_f16(d0, d1, d2, d3, aM[1][0], aM[1][1], aM[1][2], aM[1][3], U0h.z, U0h.w);
        mma_f16(d0, d1, d2, d3, aM[2][0], aM[2][1], aM[2][2], aM[2][3], U1h.x, U1h.y);
        mma_f16(d0, d1, d2, d3, aM[3][0], aM[3][1], aM[3][2], aM[3][3], U1h.z, U1h.w);

        // epilogue: 2*dot = dsum/512 (exact), reference rounding
        const int c0 = g * 8 + 2 * tig;
        const float se0 = sSe[c0], se1 = sSe[c0 + 1];
        float q00 = __fadd_rn(__fsub_rn(sz0, __fmul_rn(INV_2SCALE, d0)), se0);
        float q01 = __fadd_rn(__fsub_rn(sz0, __fmul_rn(INV_2SCALE, d1)), se1);
        float q10 = __fadd_rn(__fsub_rn(sz1, __fmul_rn(INV_2SCALE, d2)), se0);
        float q11 = __fadd_rn(__fsub_rn(sz1, __fmul_rn(INV_2SCALE, d3)), se1);
        if (q00 < best0) { best0 = q00; idx0 = c0; }
        if (q01 < best0) { best0 = q01; idx0 = c0 + 1; }
        if (q10 < best1) { best1 = q10; idx1 = c0; }
        if (q11 < best1) { best1 = q11; idx1 = c0 + 1; }
    }

    // ---- cross-lane argmin over the quad, first-index tie-break ----
    #pragma unroll
    for (int off = 1; off <= 2; off <<= 1) {
        float ov0 = __shfl_xor_sync(0xFFFFFFFFu, best0, off);
        int   oi0 = __shfl_xor_sync(0xFFFFFFFFu, idx0, off);
        float ov1 = __shfl_xor_sync(0xFFFFFFFFu, best1, off);
        int   oi1 = __shfl_xor_sync(0xFFFFFFFFu, idx1, off);
        if (ov0 < best0 || (ov0 == best0 && oi0 < idx0)) { best0 = ov0; idx0 = oi0; }
        if (ov1 < best1 || (ov1 == best1 && oi1 < idx1)) { best1 = ov1; idx1 = oi1; }
    }
    if (tig == 0) {
        sIdx[r0] = idx0;
        sIdx[r1] = idx1;
    }
    __syncthreads();

    // ---- cooperative gather of selected code rows (coalesced, swizzled) ----
    #pragma unroll 2
    for (int i = tid; i < QB * (DIM / 4); i += THREADS) {
        int row = i >> 4, c4 = i & 15;
        const float4* src = reinterpret_cast<const float4*>(emb + (size_t)sIdx[row] * DIM);
        sG4[row * 16 + ((c4 + row) & 15)] = __ldg(src + c4);
    }
    __syncthreads();

    // ---- outputs: STE, idx, loss partial (smem-fed) ----
    double lsum = 0.0;
    if (tid < QB) {
        const int n = qb + tid;
        const int bidx = sIdx[tid];
        const int w = n & 31;
        const int h = (n >> 5) & 31;
        const int b = n >> 10;
        const size_t obase = (size_t)b * 65536 + (size_t)h * 32 + w;

        const float4* zr4 = reinterpret_cast<const float4*>(&sBuf[tid * PAD]);
        #pragma unroll 2
        for (int j = 0; j < DIM / 4; ++j) {
            float4 zv = zr4[j];
            float4 ev = sG4[tid * 16 + ((j + tid) & 15)];   // element j of row tid
            float zq[4] = {zv.x, zv.y, zv.z, zv.w};
            float eq[4] = {ev.x, ev.y, ev.z, ev.w};
            #pragma unroll
            for (int u = 0; u < 4; ++u) {
                const int d = 4 * j + u;
                float diff = __fsub_rn(eq[u], zq[u]);
                out[obase + (size_t)d * 1024] = __fadd_rn(zq[u], diff);  // STE
                lsum += (double)diff * (double)diff;
            }
        }
        out[OUT_IDX_OFF + (size_t)n] = (float)bidx;
    }

    // ---- loss reduction + last-block finalize ----
    #pragma unroll
    for (int off = 16; off > 0; off >>= 1)
        lsum += __shfl_down_sync(0xFFFFFFFFu, lsum, off);
    if (lane == 0) sRed[wid] = lsum;
    __syncthreads();
    if (tid == 0) {
        double v = 0.0;
        #pragma unroll
        for (int i = 0; i < THREADS / 32; ++i) v += sRed[i];
        g_partial[blockIdx.x] = v;
        __threadfence();
        unsigned old = atomicAdd(&g_done, 1u);
        if ((old & (NBLOCKS - 1)) == (NBLOCKS - 1)) *sLast = 1;
    }
    __syncthreads();

    if (*sLast && wid == 0) {
        __threadfence();
        double v = 0.0;
        #pragma unroll
        for (int i = 0; i < NBLOCKS / 32; ++i)   // fixed order: deterministic
            v += g_partial[lane + i * 32];
        #pragma unroll
        for (int off = 16; off > 0; off >>= 1)
            v += __shfl_down_sync(0xFFFFFFFFu, v, off);
        if (lane == 0) {
            double mean = v / (double)OUT_QV_ELEMS;
            out[OUT_LOSS_OFF] = (float)(mean * 0.25 + mean * 1.0);
        }
    }
}

extern "C" void kernel_launch(void* const* d_in, const int* in_sizes, int n_in,
                              void* d_out, int out_size) {
    const float* z   = (const float*)d_in[0];
    const float* emb = (const float*)d_in[1];
    float* out = (float*)d_out;

    cudaFuncSetAttribute(vq_main, cudaFuncAttributeMaxDynamicSharedMemorySize, SMEM_MAIN);

    vq_prep<<<(NGROUP * 2 * 32 + 255) / 256, 256>>>(emb);
    vq_main<<<NBLOCKS, THREADS, SMEM_MAIN>>>(z, emb, out);
}

// round 16
// speedup vs baseline: 1.6228x; 1.0808x over previous
#include <cuda_runtime.h>
#include <cuda_fp16.h>
#include <cstdint>

// Shapes
#define N_Q    65536
#define DIM    64
#define K_EMB  1024
#define QB     128
#define THREADS 256
#define NTILES (N_Q / QB)     // 512
#define GRIDSZ 444            // 148 SMs x 3 CTAs (all co-resident at occ 3)
#define EXTRA  (NTILES - GRIDSZ)   // 68 CTAs run a second tile
#define NGROUP 128
#define PAD    68

#define ESCALE      1024.0f
#define INV_2SCALE  (1.0f / 512.0f)

#define OUT_QV_ELEMS  (64ULL * 64ULL * 32ULL * 32ULL)
#define OUT_IDX_OFF   4194304ULL
#define OUT_LOSS_OFF  4259840ULL

// ---- dynamic smem layout (byte offsets, 16B-aligned blocks) ----
#define SRED_OFF    0        // double[8]
#define SLAST_OFF   64       // int
#define SIDX_OFF    80       // int[128]
#define SSZ_OFF     592      // float[128]
#define SSE_OFF     1104     // float[1024]
#define SBUF_OFF    5200     // float[128*68]  z tile (padded)
#define SG_OFF      40016    // float4[128*16] gather buffer (32KB)
#define SMEM_MAIN   72784

// device scratch (zero-initialized at load; counters strictly monotonic:
// each launch adds exactly GRIDSZ, so values stay multiples of GRIDSZ at
// launch boundaries -> graph-replay-safe epochs)
__device__ float    g_se2[K_EMB];
__device__ uint4    g_bh4[NGROUP * 2 * 32];   // hi  frags: (g*2+h)*32+lane
__device__ uint4    g_bm4[NGROUP * 2 * 32];   // mid frags
__device__ double   g_partial[GRIDSZ];
__device__ unsigned g_sync;                   // prep barrier counter
__device__ unsigned g_fin;                    // completion counter

__device__ __forceinline__ uint32_t pack_h2(__half lo, __half hi) {
    __half2 h = __halves2half2(lo, hi);
    return *reinterpret_cast<uint32_t*>(&h);
}

__device__ __forceinline__ void mma_f16(float& d0, float& d1, float& d2, float& d3,
                                        uint32_t a0, uint32_t a1, uint32_t a2, uint32_t a3,
                                        uint32_t b0, uint32_t b1) {
    asm volatile(
        "mma.sync.aligned.m16n8k16.row.col.f32.f16.f16.f32 "
        "{%0,%1,%2,%3}, {%4,%5,%6,%7}, {%8,%9}, {%0,%1,%2,%3};\n"
        : "+f"(d0), "+f"(d1), "+f"(d2), "+f"(d3)
        : "r"(a0), "r"(a1), "r"(a2), "r"(a3), "r"(b0), "r"(b1));
}

// ---------------------------------------------------------------------------
// Single persistent kernel.
// ---------------------------------------------------------------------------
__global__ void __launch_bounds__(THREADS, 3)
vq_main(const float* __restrict__ z,
        const float* __restrict__ emb,
        float* __restrict__ out) {
    extern __shared__ __align__(16) char sm[];
    double* sRed  = reinterpret_cast<double*>(sm + SRED_OFF);
    int*    sLast = reinterpret_cast<int*>(sm + SLAST_OFF);
    int*    sIdx  = reinterpret_cast<int*>(sm + SIDX_OFF);
    float*  sSz   = reinterpret_cast<float*>(sm + SSZ_OFF);
    float*  sSe   = reinterpret_cast<float*>(sm + SSE_OFF);
    float*  sBuf  = reinterpret_cast<float*>(sm + SBUF_OFF);
    float4* sG4   = reinterpret_cast<float4*>(sm + SG_OFF);

    const int tid  = threadIdx.x;
    const int wid  = tid >> 5;
    const int lane = tid & 31;
    const int gid  = lane >> 2;
    const int tig  = lane & 3;

    if (tid == 0) *sLast = 0;

    // ================= inline prep: fragments + se2 (grid-cooperative) ======
    for (int t = blockIdx.x * THREADS + tid; t < NGROUP * 2 * 32; t += GRIDSZ * THREADS) {
        const int g = t >> 6;
        const int h = (t >> 5) & 1;
        const int l = t & 31;
        const int fgid = l >> 2, ftig = l & 3;
        const float* e = emb + (g * 8 + fgid) * DIM;
        const int k0 = (2 * h) * 16 + ftig * 2;
        const int k1 = (2 * h + 1) * 16 + ftig * 2;

        float v[8] = { e[k0] * ESCALE, e[k0 + 1] * ESCALE,
                       e[k0 + 8] * ESCALE, e[k0 + 9] * ESCALE,
                       e[k1] * ESCALE, e[k1 + 1] * ESCALE,
                       e[k1 + 8] * ESCALE, e[k1 + 9] * ESCALE };
        __half hh[8], mm[8];
        #pragma unroll
        for (int i = 0; i < 8; ++i) {
            hh[i] = __float2half_rn(v[i]);
            mm[i] = __float2half_rn(__fsub_rn(v[i], __half2float(hh[i])));
        }
        uint4 uh, um;
        uh.x = pack_h2(hh[0], hh[1]); uh.y = pack_h2(hh[2], hh[3]);
        uh.z = pack_h2(hh[4], hh[5]); uh.w = pack_h2(hh[6], hh[7]);
        um.x = pack_h2(mm[0], mm[1]); um.y = pack_h2(mm[2], mm[3]);
        um.z = pack_h2(mm[4], mm[5]); um.w = pack_h2(mm[6], mm[7]);
        g_bh4[t] = uh;
        g_bm4[t] = um;
    }
    for (int t = blockIdx.x * THREADS + tid; t < K_EMB; t += GRIDSZ * THREADS) {
        const float* e = emb + t * DIM;
        float s = 0.0f;
        #pragma unroll
        for (int j = 0; j < DIM; ++j)
            s = __fadd_rn(s, __fmul_rn(e[j], e[j]));
        g_se2[t] = s;
    }

    // ================= grid barrier (all GRIDSZ CTAs resident at occ 3) =====
    __syncthreads();
    if (tid == 0) {
        __threadfence();
        unsigned old = atomicAdd(&g_sync, 1u);
        unsigned target = (old / GRIDSZ) * GRIDSZ + GRIDSZ;
        volatile unsigned* p = &g_sync;
        while (*p < target) { }
        __threadfence();
    }
    __syncthreads();

    // se -> smem once per CTA
    #pragma unroll 4
    for (int i = tid; i < K_EMB; i += THREADS) sSe[i] = g_se2[i];

    double lsum = 0.0;
    const int ntile = (blockIdx.x < EXTRA) ? 2 : 1;

    for (int ti = 0; ti < ntile; ++ti) {
        const int tile = (ti == 0) ? blockIdx.x : (GRIDSZ + blockIdx.x);
        const int qb   = tile * QB;
        __syncthreads();   // protect sBuf/sG4 reuse across tiles

        // ---- stage z tile ----
        {
            const float4* src = reinterpret_cast<const float4*>(z + (size_t)qb * DIM);
            #pragma unroll 4
            for (int i = tid; i < QB * (DIM / 4); i += THREADS) {
                int row = i >> 4, c4 = i & 15;
                float4 v = __ldg(src + i);
                *reinterpret_cast<float4*>(&sBuf[row * PAD + 4 * c4]) = v;
            }
        }
        __syncthreads();

        // row norms (square-then-add, sequential; reference style)
        if (tid < QB) {
            const float* r = &sBuf[tid * PAD];
            float s = 0.0f;
            #pragma unroll
            for (int j = 0; j < DIM; ++j)
                s = __fadd_rn(s, __fmul_rn(r[j], r[j]));
            sSz[tid] = s;
        }
        __syncthreads();

        // ---- A fragments (fp16 hi & mid splits) ----
        uint32_t aH[4][4], aM[4][4];
        const int r0 = wid * 16 + gid;
        const int r1 = r0 + 8;
        #pragma unroll
        for (int s = 0; s < 4; ++s) {
            const int k = s * 16 + tig * 2;
            const float v[4][2] = {
                { sBuf[r0 * PAD + k],     sBuf[r0 * PAD + k + 1] },
                { sBuf[r1 * PAD + k],     sBuf[r1 * PAD + k + 1] },
                { sBuf[r0 * PAD + k + 8], sBuf[r0 * PAD + k + 9] },
                { sBuf[r1 * PAD + k + 8], sBuf[r1 * PAD + k + 9] },
            };
            #pragma unroll
            for (int q = 0; q < 4; ++q) {
                __half h0 = __float2half_rn(v[q][0]);
                __half h1 = __float2half_rn(v[q][1]);
                __half m0 = __float2half_rn(__fsub_rn(v[q][0], __half2float(h0)));
                __half m1 = __float2half_rn(__fsub_rn(v[q][1], __half2float(h1)));
                aH[s][q] = pack_h2(h0, h1);
                aM[s][q] = pack_h2(m0, m1);
            }
        }
        const float sz0 = sSz[r0];
        const float sz1 = sSz[r1];

        float best0 = 3.4e38f, best1 = 3.4e38f;
        int   idx0  = 0,       idx1  = 0;

        // ---- main loop: 128 n-groups, 12 MMA each ----
        #pragma unroll 2
        for (int g = 0; g < NGROUP; ++g) {
            const uint4 U0h = __ldg(&g_bh4[(g * 2) * 32 + lane]);
            const uint4 U1h = __ldg(&g_bh4[(g * 2 + 1) * 32 + lane]);
            const uint4 U0m = __ldg(&g_bm4[(g * 2) * 32 + lane]);
            const uint4 U1m = __ldg(&g_bm4[(g * 2 + 1) * 32 + lane]);

            float d0 = 0.f, d1 = 0.f, d2 = 0.f, d3 = 0.f;
            mma_f16(d0, d1, d2, d3, aH[0][0], aH[0][1], aH[0][2], aH[0][3], U0h.x, U0h.y);
            mma_f16(d0, d1, d2, d3, aH[1][0], aH[1][1], aH[1][2], aH[1][3], U0h.z, U0h.w);
            mma_f16(d0, d1, d2, d3, aH[2][0], aH[2][1], aH[2][2], aH[2][3], U1h.x, U1h.y);
            mma_f16(d0, d1, d2, d3, aH[3][0], aH[3][1], aH[3][2], aH[3][3], U1h.z, U1h.w);
            mma_f16(d0, d1, d2, d3, aH[0][0], aH[0][1], aH[0][2], aH[0][3], U0m.x, U0m.y);
            mma_f16(d0, d1, d2, d3, aH[1][0], aH[1][1], aH[1][2], aH[1][3], U0m.z, U0m.w);
            mma_f16(d0, d1, d2, d3, aH[2][0], aH[2][1], aH[2][2], aH[2][3], U1m.x, U1m.y);
            mma_f16(d0, d1, d2, d3, aH[3][0], aH[3][1], aH[3][2], aH[3][3], U1m.z, U1m.w);
            mma_f16(d0, d1, d2, d3, aM[0][0], aM[0][1], aM[0][2], aM[0][3], U0h.x, U0h.y);
            mma_f16(d0, d1, d2, d3, aM[1][0], aM[1][1], aM[1][2], aM[1][3], U0h.z, U0h.w);
            mma_f16(d0, d1, d2, d3, aM[2][0], aM[2][1], aM[2][2], aM[2][3], U1h.x, U1h.y);
            mma_f16(d0, d1, d2, d3, aM[3][0], aM[3][1], aM[3][2], aM[3][3], U1h.z, U1h.w);

            const int c0 = g * 8 + 2 * tig;
            const float se0 = sSe[c0], se1 = sSe[c0 + 1];
            float q00 = __fadd_rn(__fsub_rn(sz0, __fmul_rn(INV_2SCALE, d0)), se0);
            float q01 = __fadd_rn(__fsub_rn(sz0, __fmul_rn(INV_2SCALE, d1)), se1);
            float q10 = __fadd_rn(__fsub_rn(sz1, __fmul_rn(INV_2SCALE, d2)), se0);
            float q11 = __fadd_rn(__fsub_rn(sz1, __fmul_rn(INV_2SCALE, d3)), se1);
            if (q00 < best0) { best0 = q00; idx0 = c0; }
            if (q01 < best0) { best0 = q01; idx0 = c0 + 1; }
            if (q10 < best1) { best1 = q10; idx1 = c0; }
            if (q11 < best1) { best1 = q11; idx1 = c0 + 1; }
        }

        // ---- cross-lane argmin, first-index tie-break ----
        #pragma unroll
        for (int off = 1; off <= 2; off <<= 1) {
            float ov0 = __shfl_xor_sync(0xFFFFFFFFu, best0, off);
            int   oi0 = __shfl_xor_sync(0xFFFFFFFFu, idx0, off);
            float ov1 = __shfl_xor_sync(0xFFFFFFFFu, best1, off);
            int   oi1 = __shfl_xor_sync(0xFFFFFFFFu, idx1, off);
            if (ov0 < best0 || (ov0 == best0 && oi0 < idx0)) { best0 = ov0; idx0 = oi0; }
            if (ov1 < best1 || (ov1 == best1 && oi1 < idx1)) { best1 = ov1; idx1 = oi1; }
        }
        if (tig == 0) {
            sIdx[r0] = idx0;
            sIdx[r1] = idx1;
        }
        __syncthreads();

        // ---- cooperative gather of selected code rows (coalesced, swizzled) ----
        #pragma unroll 2
        for (int i = tid; i < QB * (DIM / 4); i += THREADS) {
            int row = i >> 4, c4 = i & 15;
            const float4* src = reinterpret_cast<const float4*>(emb + (size_t)sIdx[row] * DIM);
            sG4[row * 16 + ((c4 + row) & 15)] = __ldg(src + c4);
        }
        __syncthreads();

        // ---- outputs: STE, idx, loss partial (smem-fed) ----
        if (tid < QB) {
            const int n = qb + tid;
            const int bidx = sIdx[tid];
            const int w = n & 31;
            const int h = (n >> 5) & 31;
            const int b = n >> 10;
            const size_t obase = (size_t)b * 65536 + (size_t)h * 32 + w;

            const float4* zr4 = reinterpret_cast<const float4*>(&sBuf[tid * PAD]);
            #pragma unroll 2
            for (int j = 0; j < DIM / 4; ++j) {
                float4 zv = zr4[j];
                float4 ev = sG4[tid * 16 + ((j + tid) & 15)];   // element j of row tid
                float zq[4] = {zv.x, zv.y, zv.z, zv.w};
                float eq[4] = {ev.x, ev.y, ev.z, ev.w};
                #pragma unroll
                for (int u = 0; u < 4; ++u) {
                    const int d = 4 * j + u;
                    float diff = __fsub_rn(eq[u], zq[u]);
                    out[obase + (size_t)d * 1024] = __fadd_rn(zq[u], diff);  // STE
                    lsum += (double)diff * (double)diff;
                }
            }
            out[OUT_IDX_OFF + (size_t)n] = (float)bidx;
        }
    }

    // ================= loss reduction + last-CTA finalize ===================
    #pragma unroll
    for (int off = 16; off > 0; off >>= 1)
        lsum += __shfl_down_sync(0xFFFFFFFFu, lsum, off);
    if (lane == 0) sRed[wid] = lsum;
    __syncthreads();
    if (tid == 0) {
        double v = 0.0;
        #pragma unroll
        for (int i = 0; i < THREADS / 32; ++i) v += sRed[i];
        g_partial[blockIdx.x] = v;
        __threadfence();
        unsigned old = atomicAdd(&g_fin, 1u);
        if (((old + 1u) % GRIDSZ) == 0u) *sLast = 1;
    }
    __syncthreads();

    if (*sLast && wid == 0) {
        __threadfence();
        double v = 0.0;
        #pragma unroll 1
        for (int i = 0; i < (GRIDSZ + 31) / 32; ++i) {   // fixed order
            int idx = lane + i * 32;
            if (idx < GRIDSZ) v += g_partial[idx];
        }
        #pragma unroll
        for (int off = 16; off > 0; off >>= 1)
            v += __shfl_down_sync(0xFFFFFFFFu, v, off);
        if (lane == 0) {
            double mean = v / (double)OUT_QV_ELEMS;
            out[OUT_LOSS_OFF] = (float)(mean * 0.25 + mean * 1.0);
        }
    }
}

extern "C" void kernel_launch(void* const* d_in, const int* in_sizes, int n_in,
                              void* d_out, int out_size) {
    const float* z   = (const float*)d_in[0];
    const float* emb = (const float*)d_in[1];
    float* out = (float*)d_out;

    cudaFuncSetAttribute(vq_main, cudaFuncAttributeMaxDynamicSharedMemorySize, SMEM_MAIN);

    vq_main<<<GRIDSZ, THREADS, SMEM_MAIN>>>(z, emb, out);
}

// round 17
// speedup vs baseline: 1.7049x; 1.0506x over previous
#include <cuda_runtime.h>
#include <cuda_fp16.h>
#include <cstdint>

// Shapes
#define N_Q    65536
#define DIM    64
#define K_EMB  1024
#define QB     128
#define THREADS 256
#define NTILES (N_Q / QB)     // 512
#define GRIDSZ 444            // 148 SMs x 3 CTAs, all co-resident (proven R15/16)
#define LTILES (NTILES - GRIDSZ)   // 68 leftover tiles
#define NSEG   8              // code segments per leftover tile
#define NJOBS  (LTILES * NSEG)     // 544
#define NGROUP 128
#define PAD    68

#define ESCALE      1024.0f
#define INV_2SCALE  (1.0f / 512.0f)

#define OUT_QV_ELEMS  (64ULL * 64ULL * 32ULL * 32ULL)
#define OUT_IDX_OFF   4194304ULL
#define OUT_LOSS_OFF  4259840ULL

// ---- dynamic smem layout ----
#define SRED_OFF    0        // double[8]
#define SLAST_OFF   64       // int
#define SJOB_OFF    68       // int
#define SIDX_OFF    80       // int[128]
#define SSZ_OFF     592      // float[128]
#define SSE_OFF     1104     // float[1024]
#define SBUF_OFF    5200     // float[128*68]  z tile (padded)
#define SG_OFF      40016    // float4[128*16] gather buffer (32KB)
#define SMEM_MAIN   72784

// device scratch (zero-initialized at load)
__device__ float    g_se2[K_EMB];
__device__ uint4    g_bh4[NGROUP * 2 * 32];
__device__ uint4    g_bm4[NGROUP * 2 * 32];
__device__ unsigned long long g_key[N_Q];   // only leftover range used
__device__ double   g_partial[NTILES];      // per-tile loss partials
__device__ unsigned g_arr[LTILES];          // per-tile job arrivals (reset each launch)
__device__ unsigned g_unit;                 // job counter (reset each launch)
__device__ unsigned g_sync;                 // prep barrier (monotonic)
__device__ unsigned g_fin;                  // completion counter (monotonic)

__device__ __forceinline__ uint32_t pack_h2(__half lo, __half hi) {
    __half2 h = __halves2half2(lo, hi);
    return *reinterpret_cast<uint32_t*>(&h);
}

__device__ __forceinline__ void mma_f16(float& d0, float& d1, float& d2, float& d3,
                                        uint32_t a0, uint32_t a1, uint32_t a2, uint32_t a3,
                                        uint32_t b0, uint32_t b1) {
    asm volatile(
        "mma.sync.aligned.m16n8k16.row.col.f32.f16.f16.f32 "
        "{%0,%1,%2,%3}, {%4,%5,%6,%7}, {%8,%9}, {%0,%1,%2,%3};\n"
        : "+f"(d0), "+f"(d1), "+f"(d2), "+f"(d3)
        : "r"(a0), "r"(a1), "r"(a2), "r"(a3), "r"(b0), "r"(b1));
}

// ---------------------------------------------------------------------------
__global__ void __launch_bounds__(THREADS, 3)
vq_main(const float* __restrict__ z,
        const float* __restrict__ emb,
        float* __restrict__ out) {
    extern __shared__ __align__(16) char sm[];
    double* sRed  = reinterpret_cast<double*>(sm + SRED_OFF);
    int*    sLast = reinterpret_cast<int*>(sm + SLAST_OFF);
    int*    sJob  = reinterpret_cast<int*>(sm + SJOB_OFF);
    int*    sIdx  = reinterpret_cast<int*>(sm + SIDX_OFF);
    float*  sSz   = reinterpret_cast<float*>(sm + SSZ_OFF);
    float*  sSe   = reinterpret_cast<float*>(sm + SSE_OFF);
    float*  sBuf  = reinterpret_cast<float*>(sm + SBUF_OFF);
    float4* sG4   = reinterpret_cast<float4*>(sm + SG_OFF);

    const int tid  = threadIdx.x;
    const int wid  = tid >> 5;
    const int lane = tid & 31;
    const int gid  = lane >> 2;
    const int tig  = lane & 3;

    if (tid == 0) *sLast = 0;

    // ============ prep: fragments + se2 + key init + counter resets ========
    for (int t = blockIdx.x * THREADS + tid; t < NGROUP * 2 * 32; t += GRIDSZ * THREADS) {
        const int g = t >> 6;
        const int h = (t >> 5) & 1;
        const int l = t & 31;
        const int fgid = l >> 2, ftig = l & 3;
        const float* e = emb + (g * 8 + fgid) * DIM;
        const int k0 = (2 * h) * 16 + ftig * 2;
        const int k1 = (2 * h + 1) * 16 + ftig * 2;
        float v[8] = { e[k0] * ESCALE, e[k0 + 1] * ESCALE,
                       e[k0 + 8] * ESCALE, e[k0 + 9] * ESCALE,
                       e[k1] * ESCALE, e[k1 + 1] * ESCALE,
                       e[k1 + 8] * ESCALE, e[k1 + 9] * ESCALE };
        __half hh[8], mm[8];
        #pragma unroll
        for (int i = 0; i < 8; ++i) {
            hh[i] = __float2half_rn(v[i]);
            mm[i] = __float2half_rn(__fsub_rn(v[i], __half2float(hh[i])));
        }
        uint4 uh, um;
        uh.x = pack_h2(hh[0], hh[1]); uh.y = pack_h2(hh[2], hh[3]);
        uh.z = pack_h2(hh[4], hh[5]); uh.w = pack_h2(hh[6], hh[7]);
        um.x = pack_h2(mm[0], mm[1]); um.y = pack_h2(mm[2], mm[3]);
        um.z = pack_h2(mm[4], mm[5]); um.w = pack_h2(mm[6], mm[7]);
        g_bh4[t] = uh;
        g_bm4[t] = um;
    }
    for (int t = blockIdx.x * THREADS + tid; t < K_EMB; t += GRIDSZ * THREADS) {
        const float* e = emb + t * DIM;
        float s = 0.0f;
        #pragma unroll
        for (int j = 0; j < DIM; ++j)
            s = __fadd_rn(s, __fmul_rn(e[j], e[j]));
        g_se2[t] = s;
    }
    // leftover-query key init (grid-strided)
    for (int t = blockIdx.x * THREADS + tid; t < LTILES * QB; t += GRIDSZ * THREADS)
        g_key[GRIDSZ * QB + t] = 0xFFFFFFFFFFFFFFFFULL;
    // counter resets by CTA0/tid0 only (self-ordered by its own fence at barrier)
    if (blockIdx.x == 0 && tid == 0) {
        g_unit = 0u;
        for (int i = 0; i < LTILES; ++i) g_arr[i] = 0u;
    }

    // ============ grid barrier (all GRIDSZ CTAs resident) ===================
    __syncthreads();
    if (tid == 0) {
        __threadfence();
        unsigned old = atomicAdd(&g_sync, 1u);
        unsigned target = (old / GRIDSZ) * GRIDSZ + GRIDSZ;
        volatile unsigned* p = &g_sync;
        while (*p < target) { }
        __threadfence();
    }
    __syncthreads();

    #pragma unroll 4
    for (int i = tid; i < K_EMB; i += THREADS) sSe[i] = g_se2[i];

    const int r0 = wid * 16 + gid;
    const int r1 = r0 + 8;

    // ======================= main tile (tile = blockIdx.x) ==================
    {
        const int qb = blockIdx.x * QB;
        __syncthreads();
        {
            const float4* src = reinterpret_cast<const float4*>(z + (size_t)qb * DIM);
            #pragma unroll 4
            for (int i = tid; i < QB * (DIM / 4); i += THREADS) {
                int row = i >> 4, c4 = i & 15;
                float4 v = __ldg(src + i);
                *reinterpret_cast<float4*>(&sBuf[row * PAD + 4 * c4]) = v;
            }
        }
        __syncthreads();
        if (tid < QB) {
            const float* r = &sBuf[tid * PAD];
            float s = 0.0f;
            #pragma unroll
            for (int j = 0; j < DIM; ++j)
                s = __fadd_rn(s, __fmul_rn(r[j], r[j]));
            sSz[tid] = s;
        }
        __syncthreads();

        uint32_t aH[4][4], aM[4][4];
        #pragma unroll
        for (int s = 0; s < 4; ++s) {
            const int k = s * 16 + tig * 2;
            const float v[4][2] = {
                { sBuf[r0 * PAD + k],     sBuf[r0 * PAD + k + 1] },
                { sBuf[r1 * PAD + k],     sBuf[r1 * PAD + k + 1] },
                { sBuf[r0 * PAD + k + 8], sBuf[r0 * PAD + k + 9] },
                { sBuf[r1 * PAD + k + 8], sBuf[r1 * PAD + k + 9] },
            };
            #pragma unroll
            for (int q = 0; q < 4; ++q) {
                __half h0 = __float2half_rn(v[q][0]);
                __half h1 = __float2half_rn(v[q][1]);
                __half m0 = __float2half_rn(__fsub_rn(v[q][0], __half2float(h0)));
                __half m1 = __float2half_rn(__fsub_rn(v[q][1], __half2float(h1)));
                aH[s][q] = pack_h2(h0, h1);
                aM[s][q] = pack_h2(m0, m1);
            }
        }
        const float sz0 = sSz[r0];
        const float sz1 = sSz[r1];

        float best0 = 3.4e38f, best1 = 3.4e38f;
        int   idx0  = 0,       idx1  = 0;

        #pragma unroll 2
        for (int g = 0; g < NGROUP; ++g) {
            const uint4 U0h = __ldg(&g_bh4[(g * 2) * 32 + lane]);
            const uint4 U1h = __ldg(&g_bh4[(g * 2 + 1) * 32 + lane]);
            const uint4 U0m = __ldg(&g_bm4[(g * 2) * 32 + lane]);
            const uint4 U1m = __ldg(&g_bm4[(g * 2 + 1) * 32 + lane]);
            float d0 = 0.f, d1 = 0.f, d2 = 0.f, d3 = 0.f;
            mma_f16(d0, d1, d2, d3, aH[0][0], aH[0][1], aH[0][2], aH[0][3], U0h.x, U0h.y);
            mma_f16(d0, d1, d2, d3, aH[1][0], aH[1][1], aH[1][2], aH[1][3], U0h.z, U0h.w);
            mma_f16(d0, d1, d2, d3, aH[2][0], aH[2][1], aH[2][2], aH[2][3], U1h.x, U1h.y);
            mma_f16(d0, d1, d2, d3, aH[3][0], aH[3][1], aH[3][2], aH[3][3], U1h.z, U1h.w);
            mma_f16(d0, d1, d2, d3, aH[0][0], aH[0][1], aH[0][2], aH[0][3], U0m.x, U0m.y);
            mma_f16(d0, d1, d2, d3, aH[1][0], aH[1][1], aH[1][2], aH[1][3], U0m.z, U0m.w);
            mma_f16(d0, d1, d2, d3, aH[2][0], aH[2][1], aH[2][2], aH[2][3], U1m.x, U1m.y);
            mma_f16(d0, d1, d2, d3, aH[3][0], aH[3][1], aH[3][2], aH[3][3], U1m.z, U1m.w);
            mma_f16(d0, d1, d2, d3, aM[0][0], aM[0][1], aM[0][2], aM[0][3], U0h.x, U0h.y);
            mma_f16(d0, d1, d2, d3, aM[1][0], aM[1][1], aM[1][2], aM[1][3], U0h.z, U0h.w);
            mma_f16(d0, d1, d2, d3, aM[2][0], aM[2][1], aM[2][2], aM[2][3], U1h.x, U1h.y);
            mma_f16(d0, d1, d2, d3, aM[3][0], aM[3][1], aM[3][2], aM[3][3], U1h.z, U1h.w);

            const int c0 = g * 8 + 2 * tig;
            const float se0 = sSe[c0], se1 = sSe[c0 + 1];
            float q00 = __fadd_rn(__fsub_rn(sz0, __fmul_rn(INV_2SCALE, d0)), se0);
            float q01 = __fadd_rn(__fsub_rn(sz0, __fmul_rn(INV_2SCALE, d1)), se1);
            float q10 = __fadd_rn(__fsub_rn(sz1, __fmul_rn(INV_2SCALE, d2)), se0);
            float q11 = __fadd_rn(__fsub_rn(sz1, __fmul_rn(INV_2SCALE, d3)), se1);
            if (q00 < best0) { best0 = q00; idx0 = c0; }
            if (q01 < best0) { best0 = q01; idx0 = c0 + 1; }
            if (q10 < best1) { best1 = q10; idx1 = c0; }
            if (q11 < best1) { best1 = q11; idx1 = c0 + 1; }
        }

        #pragma unroll
        for (int off = 1; off <= 2; off <<= 1) {
            float ov0 = __shfl_xor_sync(0xFFFFFFFFu, best0, off);
            int   oi0 = __shfl_xor_sync(0xFFFFFFFFu, idx0, off);
            float ov1 = __shfl_xor_sync(0xFFFFFFFFu, best1, off);
            int   oi1 = __shfl_xor_sync(0xFFFFFFFFu, idx1, off);
            if (ov0 < best0 || (ov0 == best0 && oi0 < idx0)) { best0 = ov0; idx0 = oi0; }
            if (ov1 < best1 || (ov1 == best1 && oi1 < idx1)) { best1 = ov1; idx1 = oi1; }
        }
        if (tig == 0) { sIdx[r0] = idx0; sIdx[r1] = idx1; }
        __syncthreads();

        // gather + outputs + per-tile loss
        #pragma unroll 2
        for (int i = tid; i < QB * (DIM / 4); i += THREADS) {
            int row = i >> 4, c4 = i & 15;
            const float4* src = reinterpret_cast<const float4*>(emb + (size_t)sIdx[row] * DIM);
            sG4[row * 16 + ((c4 + row) & 15)] = __ldg(src + c4);
        }
        __syncthreads();

        double lsum = 0.0;
        if (tid < QB) {
            const int n = qb + tid;
            const int bidx = sIdx[tid];
            const int w = n & 31;
            const int h = (n >> 5) & 31;
            const int b = n >> 10;
            const size_t obase = (size_t)b * 65536 + (size_t)h * 32 + w;
            const float4* zr4 = reinterpret_cast<const float4*>(&sBuf[tid * PAD]);
            #pragma unroll 2
            for (int j = 0; j < DIM / 4; ++j) {
                float4 zv = zr4[j];
                float4 ev = sG4[tid * 16 + ((j + tid) & 15)];
                float zq[4] = {zv.x, zv.y, zv.z, zv.w};
                float eq[4] = {ev.x, ev.y, ev.z, ev.w};
                #pragma unroll
                for (int u = 0; u < 4; ++u) {
                    const int d = 4 * j + u;
                    float diff = __fsub_rn(eq[u], zq[u]);
                    out[obase + (size_t)d * 1024] = __fadd_rn(zq[u], diff);
                    lsum += (double)diff * (double)diff;
                }
            }
            out[OUT_IDX_OFF + (size_t)n] = (float)bidx;
        }
        #pragma unroll
        for (int off = 16; off > 0; off >>= 1)
            lsum += __shfl_down_sync(0xFFFFFFFFu, lsum, off);
        if (lane == 0) sRed[wid] = lsum;
        __syncthreads();
        if (tid == 0) {
            double v = 0.0;
            #pragma unroll
            for (int i = 0; i < THREADS / 32; ++i) v += sRed[i];
            g_partial[blockIdx.x] = v;
        }
    }

    // ======================= leftover jobs (dynamic) ========================
    for (;;) {
        __syncthreads();
        if (tid == 0) *sJob = (int)atomicAdd(&g_unit, 1u);
        __syncthreads();
        const int job = *sJob;
        if (job >= NJOBS) break;

        const int ltile = job / NSEG;               // 0..67
        const int seg   = job % NSEG;               // 0..7
        const int tile  = GRIDSZ + ltile;
        const int qb    = tile * QB;

        // stage z tile + norms
        {
            const float4* src = reinterpret_cast<const float4*>(z + (size_t)qb * DIM);
            #pragma unroll 4
            for (int i = tid; i < QB * (DIM / 4); i += THREADS) {
                int row = i >> 4, c4 = i & 15;
                float4 v = __ldg(src + i);
                *reinterpret_cast<float4*>(&sBuf[row * PAD + 4 * c4]) = v;
            }
        }
        __syncthreads();
        if (tid < QB) {
            const float* r = &sBuf[tid * PAD];
            float s = 0.0f;
            #pragma unroll
            for (int j = 0; j < DIM; ++j)
                s = __fadd_rn(s, __fmul_rn(r[j], r[j]));
            sSz[tid] = s;
        }
        __syncthreads();

        uint32_t aH[4][4], aM[4][4];
        #pragma unroll
        for (int s = 0; s < 4; ++s) {
            const int k = s * 16 + tig * 2;
            const float v[4][2] = {
                { sBuf[r0 * PAD + k],     sBuf[r0 * PAD + k + 1] },
                { sBuf[r1 * PAD + k],     sBuf[r1 * PAD + k + 1] },
                { sBuf[r0 * PAD + k + 8], sBuf[r0 * PAD + k + 9] },
                { sBuf[r1 * PAD + k + 8], sBuf[r1 * PAD + k + 9] },
            };
            #pragma unroll
            for (int q = 0; q < 4; ++q) {
                __half h0 = __float2half_rn(v[q][0]);
                __half h1 = __float2half_rn(v[q][1]);
                __half m0 = __float2half_rn(__fsub_rn(v[q][0], __half2float(h0)));
                __half m1 = __float2half_rn(__fsub_rn(v[q][1], __half2float(h1)));
                aH[s][q] = pack_h2(h0, h1);
                aM[s][q] = pack_h2(m0, m1);
            }
        }
        const float sz0 = sSz[r0];
        const float sz1 = sSz[r1];

        float best0 = 3.4e38f, best1 = 3.4e38f;
        int   idx0  = 0,       idx1  = 0;

        const int gbase = seg * (NGROUP / NSEG);    // 16 groups per job
        #pragma unroll 2
        for (int gg = 0; gg < NGROUP / NSEG; ++gg) {
            const int g = gbase + gg;
            const uint4 U0h = __ldg(&g_bh4[(g * 2) * 32 + lane]);
            const uint4 U1h = __ldg(&g_bh4[(g * 2 + 1) * 32 + lane]);
            const uint4 U0m = __ldg(&g_bm4[(g * 2) * 32 + lane]);
            const uint4 U1m = __ldg(&g_bm4[(g * 2 + 1) * 32 + lane]);
            float d0 = 0.f, d1 = 0.f, d2 = 0.f, d3 = 0.f;
            mma_f16(d0, d1, d2, d3, aH[0][0], aH[0][1], aH[0][2], aH[0][3], U0h.x, U0h.y);
            mma_f16(d0, d1, d2, d3, aH[1][0], aH[1][1], aH[1][2], aH[1][3], U0h.z, U0h.w);
            mma_f16(d0, d1, d2, d3, aH[2][0], aH[2][1], aH[2][2], aH[2][3], U1h.x, U1h.y);
            mma_f16(d0, d1, d2, d3, aH[3][0], aH[3][1], aH[3][2], aH[3][3], U1h.z, U1h.w);
            mma_f16(d0, d1, d2, d3, aH[0][0], aH[0][1], aH[0][2], aH[0][3], U0m.x, U0m.y);
            mma_f16(d0, d1, d2, d3, aH[1][0], aH[1][1], aH[1][2], aH[1][3], U0m.z, U0m.w);
            mma_f16(d0, d1, d2, d3, aH[2][0], aH[2][1], aH[2][2], aH[2][3], U1m.x, U1m.y);
            mma_f16(d0, d1, d2, d3, aH[3][0], aH[3][1], aH[3][2], aH[3][3], U1m.z, U1m.w);
            mma_f16(d0, d1, d2, d3, aM[0][0], aM[0][1], aM[0][2], aM[0][3], U0h.x, U0h.y);
            mma_f16(d0, d1, d2, d3, aM[1][0], aM[1][1], aM[1][2], aM[1][3], U0h.z, U0h.w);
            mma_f16(d0, d1, d2, d3, aM[2][0], aM[2][1], aM[2][2], aM[2][3], U1h.x, U1h.y);
            mma_f16(d0, d1, d2, d3, aM[3][0], aM[3][1], aM[3][2], aM[3][3], U1h.z, U1h.w);

            const int c0 = g * 8 + 2 * tig;
            const float se0 = sSe[c0], se1 = sSe[c0 + 1];
            float q00 = __fadd_rn(__fsub_rn(sz0, __fmul_rn(INV_2SCALE, d0)), se0);
            float q01 = __fadd_rn(__fsub_rn(sz0, __fmul_rn(INV_2SCALE, d1)), se1);
            float q10 = __fadd_rn(__fsub_rn(sz1, __fmul_rn(INV_2SCALE, d2)), se0);
            float q11 = __fadd_rn(__fsub_rn(sz1, __fmul_rn(INV_2SCALE, d3)), se1);
            if (q00 < best0) { best0 = q00; idx0 = c0; }
            if (q01 < best0) { best0 = q01; idx0 = c0 + 1; }
            if (q10 < best1) { best1 = q10; idx1 = c0; }
            if (q11 < best1) { best1 = q11; idx1 = c0 + 1; }
        }

        #pragma unroll
        for (int off = 1; off <= 2; off <<= 1) {
            float ov0 = __shfl_xor_sync(0xFFFFFFFFu, best0, off);
            int   oi0 = __shfl_xor_sync(0xFFFFFFFFu, idx0, off);
            float ov1 = __shfl_xor_sync(0xFFFFFFFFu, best1, off);
            int   oi1 = __shfl_xor_sync(0xFFFFFFFFu, idx1, off);
            if (ov0 < best0 || (ov0 == best0 && oi0 < idx0)) { best0 = ov0; idx0 = oi0; }
            if (ov1 < best1 || (ov1 == best1 && oi1 < idx1)) { best1 = ov1; idx1 = oi1; }
        }
        if (tig == 0) {
            // key = (d2_bits << 32) | idx : lexicographic (d2, idx) min
            unsigned long long k0 = ((unsigned long long)__float_as_uint(best0) << 32) | (unsigned)idx0;
            unsigned long long k1 = ((unsigned long long)__float_as_uint(best1) << 32) | (unsigned)idx1;
            atomicMin(&g_key[qb + r0], k0);
            atomicMin(&g_key[qb + r1], k1);
            __threadfence();
        }
        __syncthreads();

        // arrival: 8th job of this tile runs the epilogue (slab holds this tile)
        if (tid == 0) {
            unsigned a = atomicAdd(&g_arr[ltile], 1u);
            *sJob = (a == NSEG - 1) ? -1 : -2;   // reuse sJob as winner flag
        }
        __syncthreads();
        if (*sJob == -1) {
            if (tid < QB) {
                unsigned long long key = atomicAdd(&g_key[qb + tid], 0ULL);  // L2-direct read
                sIdx[tid] = (int)(key & 0xFFFFFFFFULL);
            }
            __syncthreads();
            #pragma unroll 2
            for (int i = tid; i < QB * (DIM / 4); i += THREADS) {
                int row = i >> 4, c4 = i & 15;
                const float4* src = reinterpret_cast<const float4*>(emb + (size_t)sIdx[row] * DIM);
                sG4[row * 16 + ((c4 + row) & 15)] = __ldg(src + c4);
            }
            __syncthreads();

            double lsum = 0.0;
            if (tid < QB) {
                const int n = qb + tid;
                const int bidx = sIdx[tid];
                const int w = n & 31;
                const int h = (n >> 5) & 31;
                const int b = n >> 10;
                const size_t obase = (size_t)b * 65536 + (size_t)h * 32 + w;
                const float4* zr4 = reinterpret_cast<const float4*>(&sBuf[tid * PAD]);
                #pragma unroll 2
                for (int j = 0; j < DIM / 4; ++j) {
                    float4 zv = zr4[j];
                    float4 ev = sG4[tid * 16 + ((j + tid) & 15)];
                    float zq[4] = {zv.x, zv.y, zv.z, zv.w};
                    float eq[4] = {ev.x, ev.y, ev.z, ev.w};
                    #pragma unroll
                    for (int u = 0; u < 4; ++u) {
                        const int d = 4 * j + u;
                        float diff = __fsub_rn(eq[u], zq[u]);
                        out[obase + (size_t)d * 1024] = __fadd_rn(zq[u], diff);
                        lsum += (double)diff * (double)diff;
                    }
                }
                out[OUT_IDX_OFF + (size_t)n] = (float)bidx;
            }
            #pragma unroll
            for (int off = 16; off > 0; off >>= 1)
                lsum += __shfl_down_sync(0xFFFFFFFFu, lsum, off);
            if (lane == 0) sRed[wid] = lsum;
            __syncthreads();
            if (tid == 0) {
                double v = 0.0;
                #pragma unroll
                for (int i = 0; i < THREADS / 32; ++i) v += sRed[i];
                g_partial[tile] = v;
            }
        }
    }

    // ======================= loss finalize (last CTA) =======================
    __syncthreads();
    if (tid == 0) {
        __threadfence();
        unsigned old = atomicAdd(&g_fin, 1u);
        if (((old + 1u) % GRIDSZ) == 0u) *sLast = 1;
    }
    __syncthreads();
    if (*sLast && wid == 0) {
        __threadfence();
        double v = 0.0;
        #pragma unroll 1
        for (int i = 0; i < NTILES / 32; ++i)   // fixed order over 512 tiles
            v += g_partial[lane + i * 32];
        #pragma unroll
        for (int off = 16; off > 0; off >>= 1)
            v += __shfl_down_sync(0xFFFFFFFFu, v, off);
        if (lane == 0) {
            double mean = v / (double)OUT_QV_ELEMS;
            out[OUT_LOSS_OFF] = (float)(mean * 0.25 + mean * 1.0);
        }
    }
}

extern "C" void kernel_launch(void* const* d_in, const int* in_sizes, int n_in,
                              void* d_out, int out_size) {
    const float* z   = (const float*)d_in[0];
    const float* emb = (const float*)d_in[1];
    float* out = (float*)d_out;

    cudaFuncSetAttribute(vq_main, cudaFuncAttributeMaxDynamicSharedMemorySize, SMEM_MAIN);

    vq_main<<<GRIDSZ, THREADS, SMEM_MAIN>>>(z, emb, out);
}